// round 8
// baseline (speedup 1.0000x reference)
#include <cuda_runtime.h>
#include <math.h>

#define BB 32
#define TL 256
#define DL 512
#define HH 512
#define VV 2000
#define MM 256
#define G4 2048
#define XD 2512
#define CATD 1024
#define NSTEP 100
#define NT 256

#define SL_IH0 79          // ceil(2512/32) K-slots for Wih0
#define S_P0   95          // 79 + 16 slots for gates0
#define S_P1   32          // 16 (Whh1) + 16 (Wih1)
#define S_PL   32          // 16 (h1 half) + 16 (ctx half)
#define LROWS  2048

#define U_IH0  632         // 8 row-tiles * 79
#define U_HH0  760         // + 8*16
#define U_P1   888         // + 8*16  == 296 * 3 when nb == 296

// ---------------- persistent device state ----------------
__device__ float g_x[BB * XD];
__device__ float g_h0[BB * HH], g_c0[BB * HH], g_h1[BB * HH], g_c1[BB * HH];
__device__ float g_cat[BB * CATD];
__device__ float g_p0[(size_t)S_P0 * G4 * BB];
__device__ float g_p1[(size_t)S_P1 * G4 * BB];
__device__ float g_pl[(size_t)S_PL * LROWS * BB];
__device__ float g_clisT[(size_t)BB * MM * TL];
__device__ unsigned g_barArr = 0;
__device__ unsigned g_barGen = 0;

__device__ __forceinline__ float sigmoidf_(float x) { return 1.f / (1.f + expf(-x)); }

// ---------------- grid barrier: thread0-only fences, read-polling -------------
__device__ __forceinline__ void gsync(unsigned& gen_next) {
    __syncthreads();
    if (threadIdx.x == 0) {
        unsigned g = gen_next;
        __threadfence();   // release (cumulative over block via prior syncthreads)
        if (atomicAdd(&g_barArr, 1u) == gridDim.x - 1) {
            g_barArr = 0;
            __threadfence();               // arr reset lands before gen bump
            atomicAdd(&g_barGen, 1u);
        } else {
            volatile unsigned* gp = &g_barGen;
            while (*gp < g) __nanosleep(64);
        }
        __threadfence();   // acquire
        gen_next = g + 1;
    }
    __syncthreads();
}

// ---------------- GEMM unit: 256 rows x 32 batch, K range [k0,k1) -------------
// out[r*32+b] = sum_{k in [k0,k1)} W[r][k]*X[b][k]
__device__ void gemm_task(const float* __restrict__ W, int ldw, int mrows,
                          const float* __restrict__ X, int ldx,
                          int rbase, int k0, int k1,
                          float* __restrict__ out, float* sm) {
    float* Ws = sm;                 // 256*33
    float* Xs = sm + 256 * 33;      // 32*33
    const int tid = threadIdx.x;
    const int rowg = tid >> 3;      // 0..31 -> rows rowg*8 .. +7
    const int bg = tid & 7;         // 0..7  -> b bg*4 .. +3
    float acc[8][4] = {};
    for (int kc = k0; kc < k1; kc += 32) {
#pragma unroll
        for (int i = 0; i < 32; i++) {           // stage W: 256 rows x 32 k
            int lin = tid + i * NT;
            int row = lin >> 5, kk = lin & 31;
            int r = rbase + row, k = kc + kk;
            Ws[row * 33 + kk] = (k < k1 && r < mrows) ? W[(size_t)r * ldw + k] : 0.f;
        }
#pragma unroll
        for (int i = 0; i < 4; i++) {            // stage X: 32 b x 32 k
            int lin = tid + i * NT;
            int bb = lin >> 5, kk = lin & 31;
            int k = kc + kk;
            Xs[bb * 33 + kk] = (k < k1) ? __ldcg(&X[(size_t)bb * ldx + k]) : 0.f;
        }
        __syncthreads();
#pragma unroll
        for (int kk = 0; kk < 32; kk++) {
            float xv[4];
#pragma unroll
            for (int j = 0; j < 4; j++) xv[j] = Xs[(bg * 4 + j) * 33 + kk];
#pragma unroll
            for (int i = 0; i < 8; i++) {
                float wv = Ws[(rowg * 8 + i) * 33 + kk];
#pragma unroll
                for (int j = 0; j < 4; j++) acc[i][j] = fmaf(wv, xv[j], acc[i][j]);
            }
        }
        __syncthreads();
    }
#pragma unroll
    for (int i = 0; i < 8; i++) {
        int r = rbase + rowg * 8 + i;
        if (r < mrows) {
#pragma unroll
            for (int j = 0; j < 4; j++)
                out[(size_t)r * BB + bg * 4 + j] = acc[i][j];
        }
    }
}

// ---------------- LSTM cell: reduce partial slots + activations --------------
__device__ void cell_phase(const float* __restrict__ P, int nslots,
                           const float* __restrict__ bih, const float* __restrict__ bhh,
                           float* __restrict__ h, float* __restrict__ c,
                           float* __restrict__ hcopy) {
    int idx = blockIdx.x * NT + threadIdx.x;
    if (idx < BB * HH) {
        int b = idx & 31, j = idx >> 5;
        float g[4];
#pragma unroll
        for (int gi = 0; gi < 4; gi++) {
            int r = gi * HH + j;
            float v = bih[r] + bhh[r];
            const float* p = P + (size_t)r * BB + b;
#pragma unroll 5
            for (int s = 0; s < nslots; s++) v += __ldcg(&p[(size_t)s * G4 * BB]);
            g[gi] = v;
        }
        float ig = sigmoidf_(g[0]);
        float fg = sigmoidf_(g[1]);
        float gg = tanhf(g[2]);
        float og = sigmoidf_(g[3]);
        float cn = fg * __ldcg(&c[b * HH + j]) + ig * gg;
        float hn = og * tanhf(cn);
        c[b * HH + j] = cn;
        h[b * HH + j] = hn;
        if (hcopy) hcopy[b * CATD + j] = hn;
    }
}

// ---------------- attention for one batch (block) ----------------------------
__device__ void attn_phase(int b, const float* __restrict__ lis,
                           const float* __restrict__ Wphi, const float* __restrict__ bphi,
                           float* __restrict__ attn_out, float* sm) {
    float* h1s = sm;            // 512
    float* cd  = sm + 512;      // 256
    float* av  = sm + 768;      // 256
    float* rb  = sm + 1024;     // 256
    int tid = threadIdx.x;
    for (int i = tid; i < HH; i += NT) h1s[i] = __ldcg(&g_h1[b * HH + i]);
    __syncthreads();
    int warp = tid >> 5, lane = tid & 31;
    for (int m = warp; m < MM; m += 8) {
        const float* w = Wphi + (size_t)m * HH;
        float p = 0.f;
#pragma unroll 4
        for (int k = lane; k < HH; k += 32) p = fmaf(w[k], h1s[k], p);
#pragma unroll
        for (int o = 16; o; o >>= 1) p += __shfl_down_sync(0xffffffffu, p, o);
        if (lane == 0) cd[m] = fmaxf(p + bphi[m], 0.f);
    }
    __syncthreads();
    const float* cl = g_clisT + (size_t)b * MM * TL + tid;
    float e = 0.f;
#pragma unroll 8
    for (int m = 0; m < MM; m++) e = fmaf(cd[m], cl[(size_t)m * TL], e);
    rb[tid] = e; __syncthreads();
    for (int o = 128; o > 0; o >>= 1) { if (tid < o) rb[tid] = fmaxf(rb[tid], rb[tid + o]); __syncthreads(); }
    float mx = rb[0]; __syncthreads();
    float p = expf(e - mx);
    rb[tid] = p; __syncthreads();
    for (int o = 128; o > 0; o >>= 1) { if (tid < o) rb[tid] += rb[tid + o]; __syncthreads(); }
    float a = p / rb[0];
    av[tid] = a;
    attn_out[tid] = a;
    __syncthreads();
    const float* lb = lis + (size_t)b * TL * DL;
#pragma unroll
    for (int dd = 0; dd < 2; dd++) {
        int d = tid + dd * NT;
        float cx = 0.f;
#pragma unroll 4
        for (int t = 0; t < TL; t++) cx = fmaf(av[t], lb[(size_t)t * DL + d], cx);
        g_cat[b * CATD + HH + d] = cx;
        g_x[(size_t)b * XD + VV + d] = cx;
    }
}

// ---------------- log-softmax + feedback for one batch -----------------------
__device__ void lsm_phase(int b, const float* __restrict__ bc,
                          float* __restrict__ preds_out, float* sm) {
    float* lg = sm;             // 2048
    float* rb = sm + 2048;      // 256
    int tid = threadIdx.x;
    float lmax = -1e30f;
    for (int v = tid; v < VV; v += NT) {
        float x = bc[v];
        const float* p = g_pl + (size_t)v * BB + b;
#pragma unroll 8
        for (int s = 0; s < S_PL; s++) x += __ldcg(&p[(size_t)s * LROWS * BB]);
        lg[v] = x;
        lmax = fmaxf(lmax, x);
    }
    rb[tid] = lmax; __syncthreads();
    for (int o = 128; o > 0; o >>= 1) { if (tid < o) rb[tid] = fmaxf(rb[tid], rb[tid + o]); __syncthreads(); }
    float mx = rb[0]; __syncthreads();
    float s = 0.f;
    for (int v = tid; v < VV; v += NT) s += expf(lg[v] - mx);
    rb[tid] = s; __syncthreads();
    for (int o = 128; o > 0; o >>= 1) { if (tid < o) rb[tid] += rb[tid + o]; __syncthreads(); }
    float lse = mx + logf(rb[0]);
    for (int v = tid; v < VV; v += NT) {
        float r = lg[v] - lse;
        preds_out[(size_t)b * VV + v] = r;
        g_x[(size_t)b * XD + v] = r;
    }
}

// ---------------- one-time psi: clisT[b][m][t] --------------------------------
__device__ void psi_task(int task, const float* __restrict__ lis,
                         const float* __restrict__ Wpsi, const float* __restrict__ bpsi,
                         float* sm) {
    int b = task >> 4;
    int rem = task & 15;
    int mb = rem >> 1, tb = rem & 1;      // 8 m-tiles of 32, 2 t-tiles of 128
    float* Ws = sm;                       // 32*33
    float* Ls = sm + 32 * 33;             // 128*33
    int tid = threadIdx.x;
    int mg = tid >> 5, tg = tid & 31;
    float acc[4][4] = {};
    const float* lb = lis + (size_t)b * TL * DL;
    for (int kc = 0; kc < DL; kc += 32) {
#pragma unroll
        for (int i = 0; i < 4; i++) {
            int lin = tid + i * NT;
            int row = lin >> 5, kk = lin & 31;
            Ws[row * 33 + kk] = Wpsi[(size_t)(mb * 32 + row) * DL + kc + kk];
        }
#pragma unroll
        for (int i = 0; i < 16; i++) {
            int lin = tid + i * NT;
            int row = lin >> 5, kk = lin & 31;
            Ls[row * 33 + kk] = lb[(size_t)(tb * 128 + row) * DL + kc + kk];
        }
        __syncthreads();
#pragma unroll 8
        for (int kk = 0; kk < 32; kk++) {
            float wv[4], lv[4];
#pragma unroll
            for (int i = 0; i < 4; i++) wv[i] = Ws[(mg * 4 + i) * 33 + kk];
#pragma unroll
            for (int j = 0; j < 4; j++) lv[j] = Ls[(tg * 4 + j) * 33 + kk];
#pragma unroll
            for (int i = 0; i < 4; i++)
#pragma unroll
                for (int j = 0; j < 4; j++) acc[i][j] = fmaf(wv[i], lv[j], acc[i][j]);
        }
        __syncthreads();
    }
#pragma unroll
    for (int i = 0; i < 4; i++) {
        int m = mb * 32 + mg * 4 + i;
        float bias = bpsi[m];
#pragma unroll
        for (int j = 0; j < 4; j++) {
            int t = tb * 128 + tg * 4 + j;
            g_clisT[((size_t)b * MM + m) * TL + t] = fmaxf(acc[i][j] + bias, 0.f);
        }
    }
}

// ---------------- persistent megakernel ---------------------------------------
__global__ void __launch_bounds__(NT, 2)
speller_mega(const float* __restrict__ lis,
             const float* __restrict__ Wih0, const float* __restrict__ Whh0,
             const float* __restrict__ bih0, const float* __restrict__ bhh0,
             const float* __restrict__ Wih1, const float* __restrict__ Whh1,
             const float* __restrict__ bih1, const float* __restrict__ bhh1,
             const float* __restrict__ Wphi, const float* __restrict__ bphi,
             const float* __restrict__ Wpsi, const float* __restrict__ bpsi,
             const float* __restrict__ Wc,   const float* __restrict__ bc,
             float* __restrict__ preds, float* __restrict__ attns) {
    __shared__ float sm[256 * 33 + 32 * 33];   // 38 KB, reused per phase
    const int blk = blockIdx.x;
    const int nb = gridDim.x;
    const int gtid = blk * NT + threadIdx.x;
    const int gsz = nb * NT;

    unsigned gen_next = 0;
    if (threadIdx.x == 0) gen_next = *((volatile unsigned*)&g_barGen) + 1;

    // one-time psi (512 tasks)
    for (int t = blk; t < 512; t += nb) psi_task(t, lis, Wpsi, bpsi, sm);

    // init x0 = [onehot(0), listener[:,0,:]] and zero LSTM states
    for (int i = gtid; i < BB * XD; i += gsz) {
        int b = i / XD, k = i - b * XD;
        float v = 0.f;
        if (k == 0) v = 1.f;
        else if (k >= VV) v = lis[(size_t)b * TL * DL + (k - VV)];
        g_x[i] = v;
    }
    for (int i = gtid; i < BB * HH; i += gsz) {
        g_h0[i] = 0.f; g_c0[i] = 0.f; g_h1[i] = 0.f; g_c1[i] = 0.f;
    }
    gsync(gen_next);

    for (int step = 0; step < NSTEP; step++) {
        // P1: Wih0@x + Whh0@h0 + Whh1@h1_prev : 888 uniform units
        for (int t = blk; t < U_P1; t += nb) {
            if (t < U_IH0) {
                int tile = t / SL_IH0, slot = t - tile * SL_IH0;
                int k0 = slot * 32;
                gemm_task(Wih0, XD, G4, g_x, XD, tile * 256, k0, min(XD, k0 + 32),
                          g_p0 + (size_t)slot * G4 * BB, sm);
            } else if (t < U_HH0) {
                int v = t - U_IH0; int tile = v >> 4, slot = v & 15;
                gemm_task(Whh0, HH, G4, g_h0, HH, tile * 256, slot * 32, slot * 32 + 32,
                          g_p0 + (size_t)(SL_IH0 + slot) * G4 * BB, sm);
            } else {
                int v = t - U_HH0; int tile = v >> 4, slot = v & 15;
                gemm_task(Whh1, HH, G4, g_h1, HH, tile * 256, slot * 32, slot * 32 + 32,
                          g_p1 + (size_t)slot * G4 * BB, sm);
            }
        }
        gsync(gen_next);
        // P2: LSTM cell 0 (blocks 0..63 have work; others pass through)
        cell_phase(g_p0, S_P0, bih0, bhh0, g_h0, g_c0, nullptr);
        gsync(gen_next);
        // P3: Wih1@h0_new : 128 units
        for (int t = blk; t < 128; t += nb) {
            int tile = t >> 4, slot = t & 15;
            gemm_task(Wih1, HH, G4, g_h0, HH, tile * 256, slot * 32, slot * 32 + 32,
                      g_p1 + (size_t)(16 + slot) * G4 * BB, sm);
        }
        gsync(gen_next);
        // P4: LSTM cell 1 (also copies h1 into cat[:, :512])
        cell_phase(g_p1, S_P1, bih1, bhh1, g_h1, g_c1, g_cat);
        gsync(gen_next);
        // P5: attention (blocks 0..31) || logits h1-half (blocks 32..159)
        if (blk < 32) {
            attn_phase(blk, lis, Wphi, bphi,
                       attns + ((size_t)step * BB + blk) * TL, sm);
        } else {
            for (int u = blk - 32; u < 128; u += nb - 32) {
                int tile = u >> 4, slot = u & 15;
                gemm_task(Wc, CATD, VV, g_cat, CATD, tile * 256, slot * 32, slot * 32 + 32,
                          g_pl + (size_t)slot * LROWS * BB, sm);
            }
        }
        gsync(gen_next);
        // P6: logits context-half (128 units)
        for (int u = blk; u < 128; u += nb) {
            int tile = u >> 4, slot = u & 15;
            gemm_task(Wc, CATD, VV, g_cat, CATD, tile * 256,
                      512 + slot * 32, 512 + slot * 32 + 32,
                      g_pl + (size_t)(16 + slot) * LROWS * BB, sm);
        }
        gsync(gen_next);
        // P7: log-softmax + feedback (blocks 0..31)
        if (blk < 32) lsm_phase(blk, bc, preds + (size_t)step * BB * VV, sm);
        gsync(gen_next);
    }
}

// ---------------- host launcher ----------------------------------------------
extern "C" void kernel_launch(void* const* d_in, const int* in_sizes, int n_in,
                              void* d_out, int out_size) {
    const float* lis  = (const float*)d_in[0];
    const float* Wih0 = (const float*)d_in[1];
    const float* Whh0 = (const float*)d_in[2];
    const float* bih0 = (const float*)d_in[3];
    const float* bhh0 = (const float*)d_in[4];
    const float* Wih1 = (const float*)d_in[5];
    const float* Whh1 = (const float*)d_in[6];
    const float* bih1 = (const float*)d_in[7];
    const float* bhh1 = (const float*)d_in[8];
    const float* Wphi = (const float*)d_in[9];
    const float* bphi = (const float*)d_in[10];
    const float* Wpsi = (const float*)d_in[11];
    const float* bpsi = (const float*)d_in[12];
    const float* Wc   = (const float*)d_in[13];
    const float* bc   = (const float*)d_in[14];

    float* preds = (float*)d_out;                      // [100,32,2000]
    float* attns = preds + (size_t)NSTEP * BB * VV;    // [100,32,256]

    // Provably-resident grid: query actual occupancy of the compiled kernel.
    static int nb_cached = 0;
    if (nb_cached == 0) {
        int nsm = 0, per_sm = 0;
        cudaDeviceGetAttribute(&nsm, cudaDevAttrMultiProcessorCount, 0);
        cudaOccupancyMaxActiveBlocksPerMultiprocessor(&per_sm, speller_mega, NT, 0);
        if (per_sm < 1) per_sm = 1;
        if (per_sm > 2) per_sm = 2;
        if (nsm < 1) nsm = 148;
        nb_cached = nsm * per_sm;
    }

    speller_mega<<<nb_cached, NT>>>(lis, Wih0, Whh0, bih0, bhh0,
                                    Wih1, Whh1, bih1, bhh1,
                                    Wphi, bphi, Wpsi, bpsi, Wc, bc,
                                    preds, attns);
}

// round 9
// speedup vs baseline: 1.6866x; 1.6866x over previous
#include <cuda_runtime.h>
#include <math.h>

#define BB 32
#define TL 256
#define DL 512
#define HH 512
#define VV 2000
#define MM 256
#define G4 2048
#define XD 2512
#define CATD 1024
#define NSTEP 100

#define S_P0 5            // gates0 partial slots: 4 (Wih0) + 1 (Whh0)
#define S_P1 3            // gates1 partial slots: 1 (Whh1) + 2 (Wih1)
#define S_PL 4            // logits partial slots
#define LROWS 2048
#define CH_IH0 628        // 2512 / 4, multiple of 4 (float4-clean)

// ---------------- persistent device state (16B aligned for float4) ------------
__device__ __align__(16) float g_x[BB * XD];
__device__ __align__(16) float g_h0[BB * HH], g_h1[BB * HH];
__device__ __align__(16) float g_c0[HH * BB], g_c1[HH * BB];   // [j][b] layout!
__device__ __align__(16) float g_cat[BB * CATD];
__device__ __align__(16) float g_p0[(size_t)S_P0 * G4 * BB];
__device__ __align__(16) float g_p1[(size_t)S_P1 * G4 * BB];
__device__ __align__(16) float g_pl[(size_t)S_PL * LROWS * BB];
__device__ __align__(16) float g_clisT[(size_t)BB * MM * TL];

__device__ __forceinline__ float sigmoidf_(float x) { return 1.f / (1.f + expf(-x)); }

// ---------------------------------------------------------------------------
// init: x0 = [onehot(0), listener[:,0,:]], zero states
// ---------------------------------------------------------------------------
__global__ void k_init(const float* __restrict__ lis) {
    int i = blockIdx.x * blockDim.x + threadIdx.x;
    if (i < BB * XD) {
        int b = i / XD, k = i % XD;
        float v = 0.f;
        if (k == 0) v = 1.f;
        else if (k >= VV) v = lis[(size_t)b * TL * DL + (k - VV)];
        g_x[i] = v;
    }
    if (i < BB * HH) {
        g_h0[i] = 0.f; g_h1[i] = 0.f; g_c0[i] = 0.f; g_c1[i] = 0.f;
    }
}

// ---------------------------------------------------------------------------
// one-time psi: g_clisT[b][m][t] = relu(listener[b][t].Wpsi[m] + bpsi[m])
// grid (8, 4, 32), 128 threads  (proven in R2)
// ---------------------------------------------------------------------------
__global__ void k_psi(const float* __restrict__ lis,
                      const float* __restrict__ Wpsi,
                      const float* __restrict__ bpsi) {
    int mb = blockIdx.x, tb = blockIdx.y, b = blockIdx.z;
    int tid = threadIdx.x;
    int mg = tid >> 4, tg = tid & 15;
    __shared__ float Ws[32 * 33];
    __shared__ float Ls[64 * 33];
    float acc[4][4] = {};
    const float* lb = lis + (size_t)b * TL * DL;
    for (int kc = 0; kc < DL; kc += 32) {
#pragma unroll
        for (int i = 0; i < 8; i++) {
            int lin = tid + i * 128;
            int row = lin >> 5, kk = lin & 31;
            Ws[row * 33 + kk] = Wpsi[(size_t)(mb * 32 + row) * DL + kc + kk];
        }
#pragma unroll
        for (int i = 0; i < 16; i++) {
            int lin = tid + i * 128;
            int row = lin >> 5, kk = lin & 31;
            Ls[row * 33 + kk] = lb[(size_t)(tb * 64 + row) * DL + kc + kk];
        }
        __syncthreads();
#pragma unroll 8
        for (int kk = 0; kk < 32; kk++) {
            float wv[4], lv[4];
#pragma unroll
            for (int i = 0; i < 4; i++) wv[i] = Ws[(mg * 4 + i) * 33 + kk];
#pragma unroll
            for (int j = 0; j < 4; j++) lv[j] = Ls[(tg * 4 + j) * 33 + kk];
#pragma unroll
            for (int i = 0; i < 4; i++)
#pragma unroll
                for (int j = 0; j < 4; j++) acc[i][j] = fmaf(wv[i], lv[j], acc[i][j]);
        }
        __syncthreads();
    }
#pragma unroll
    for (int i = 0; i < 4; i++) {
        int m = mb * 32 + mg * 4 + i;
        float bias = bpsi[m];
#pragma unroll
        for (int j = 0; j < 4; j++) {
            int t = tb * 64 + tg * 4 + j;
            g_clisT[((size_t)b * MM + m) * TL + t] = fmaxf(acc[i][j] + bias, 0.f);
        }
    }
}

// ---------------------------------------------------------------------------
// GEMM tile body: 128 rows x 32 batch, K range [k0,k1), float4 staging.
// out[r*32+b] = sum_k W[r][k]*X[b][k].  k0,k1 multiples of 4; rows guarded.
// 256 threads, thread tile 4x4.
// ---------------------------------------------------------------------------
__device__ __forceinline__ void gemm_body(
        const float* __restrict__ W, int ldw, int mrows,
        const float* __restrict__ X, int ldx,
        int rbase, int k0, int k1, float* __restrict__ out) {
    __shared__ float Ws[128 * 33];
    __shared__ float Xs[32 * 33];
    const int tid = threadIdx.x;
    const int rowg = tid >> 3, bg = tid & 7;
    float acc[4][4] = {};
    for (int kc = k0; kc < k1; kc += 32) {
#pragma unroll
        for (int i = 0; i < 4; i++) {             // W: 128 rows x 32 k = 1024 quads
            int q = tid + i * 256;
            int row = q >> 3, qk = (q & 7) * 4;
            int r = rbase + row, k = kc + qk;
            float4 v = make_float4(0.f, 0.f, 0.f, 0.f);
            if (k < k1 && r < mrows)
                v = *(const float4*)(W + (size_t)r * ldw + k);
            float* d = &Ws[row * 33 + qk];
            d[0] = v.x; d[1] = v.y; d[2] = v.z; d[3] = v.w;
        }
        {                                         // X: 32 b x 32 k = 256 quads
            int q = tid;
            int bb = q >> 3, qk = (q & 7) * 4;
            int k = kc + qk;
            float4 v = make_float4(0.f, 0.f, 0.f, 0.f);
            if (k < k1)
                v = *(const float4*)(X + (size_t)bb * ldx + k);
            float* d = &Xs[bb * 33 + qk];
            d[0] = v.x; d[1] = v.y; d[2] = v.z; d[3] = v.w;
        }
        __syncthreads();
#pragma unroll 8
        for (int kk = 0; kk < 32; kk++) {
            float wv[4], xv[4];
#pragma unroll
            for (int i = 0; i < 4; i++) wv[i] = Ws[(rowg * 4 + i) * 33 + kk];
#pragma unroll
            for (int j = 0; j < 4; j++) xv[j] = Xs[(bg * 4 + j) * 33 + kk];
#pragma unroll
            for (int i = 0; i < 4; i++)
#pragma unroll
                for (int j = 0; j < 4; j++) acc[i][j] = fmaf(wv[i], xv[j], acc[i][j]);
        }
        __syncthreads();
    }
#pragma unroll
    for (int i = 0; i < 4; i++) {
        int r = rbase + rowg * 4 + i;
        if (r < mrows) {
            float4 v = make_float4(acc[i][0], acc[i][1], acc[i][2], acc[i][3]);
            *(float4*)(out + (size_t)r * BB + bg * 4) = v;
        }
    }
}

// kG0: grid (16, 6). y=0..3: Wih0 K-chunks of 628; y=4: Whh0; y=5: Whh1.
__global__ void __launch_bounds__(256) k_g0(
        const float* __restrict__ Wih0, const float* __restrict__ Whh0,
        const float* __restrict__ Whh1) {
    int tile = blockIdx.x, s = blockIdx.y;
    if (s < 4) {
        gemm_body(Wih0, XD, G4, g_x, XD, tile * 128, s * CH_IH0, (s + 1) * CH_IH0,
                  g_p0 + (size_t)s * G4 * BB);
    } else if (s == 4) {
        gemm_body(Whh0, HH, G4, g_h0, HH, tile * 128, 0, HH,
                  g_p0 + (size_t)4 * G4 * BB);
    } else {
        gemm_body(Whh1, HH, G4, g_h1, HH, tile * 128, 0, HH, g_p1);
    }
}

// kG1: grid (16, 2). Wih1 @ h0_new, K-chunks of 256 -> g_p1 slots 1,2.
__global__ void __launch_bounds__(256) k_g1(const float* __restrict__ Wih1) {
    int tile = blockIdx.x, s = blockIdx.y;
    gemm_body(Wih1, HH, G4, g_h0, HH, tile * 128, s * 256, s * 256 + 256,
              g_p1 + (size_t)(1 + s) * G4 * BB);
}

// kLogits: grid (16, 4). Wc @ cat, K-chunks of 256 -> g_pl slots 0..3.
__global__ void __launch_bounds__(256) k_glog(const float* __restrict__ Wc) {
    int tile = blockIdx.x, s = blockIdx.y;
    gemm_body(Wc, CATD, VV, g_cat, CATD, tile * 128, s * 256, s * 256 + 256,
              g_pl + (size_t)s * LROWS * BB);
}

// ---------------------------------------------------------------------------
// LSTM cell: 4096 threads (16 blocks x 256). Thread = (j, b-quad).
// Reads partials as float4, c-state in [j][b] layout (vectorized), writes h
// (b-major, 4 scalar stores).
// ---------------------------------------------------------------------------
template <int NS>
__global__ void __launch_bounds__(256) k_cell(
        const float* __restrict__ P,
        const float* __restrict__ bih, const float* __restrict__ bhh,
        float* __restrict__ h, float* __restrict__ c, float* __restrict__ hcopy) {
    int t = blockIdx.x * 256 + threadIdx.x;      // 0..4095
    int j = t >> 3, b4 = t & 7;
    float4 g[4];
#pragma unroll
    for (int gi = 0; gi < 4; gi++) {
        int r = gi * HH + j;
        float bias = bih[r] + bhh[r];
        float4 acc = make_float4(bias, bias, bias, bias);
#pragma unroll
        for (int s = 0; s < NS; s++) {
            float4 p = *(const float4*)(P + ((size_t)s * G4 + r) * BB + b4 * 4);
            acc.x += p.x; acc.y += p.y; acc.z += p.z; acc.w += p.w;
        }
        g[gi] = acc;
    }
    float4 cp = *(const float4*)(c + (size_t)j * BB + b4 * 4);
    float ig, fg, gg, og, cn, hn;
    float4 cno, hno;
#define DO_LANE(L) \
    ig = sigmoidf_(g[0].L); fg = sigmoidf_(g[1].L); \
    gg = tanhf(g[2].L);     og = sigmoidf_(g[3].L); \
    cn = fg * cp.L + ig * gg; hn = og * tanhf(cn); \
    cno.L = cn; hno.L = hn;
    DO_LANE(x) DO_LANE(y) DO_LANE(z) DO_LANE(w)
#undef DO_LANE
    *(float4*)(c + (size_t)j * BB + b4 * 4) = cno;
    int b0 = b4 * 4;
    h[(size_t)(b0 + 0) * HH + j] = hno.x;
    h[(size_t)(b0 + 1) * HH + j] = hno.y;
    h[(size_t)(b0 + 2) * HH + j] = hno.z;
    h[(size_t)(b0 + 3) * HH + j] = hno.w;
    if (hcopy) {
        hcopy[(size_t)(b0 + 0) * CATD + j] = hno.x;
        hcopy[(size_t)(b0 + 1) * CATD + j] = hno.y;
        hcopy[(size_t)(b0 + 2) * CATD + j] = hno.z;
        hcopy[(size_t)(b0 + 3) * CATD + j] = hno.w;
    }
}

// ---------------------------------------------------------------------------
// Attention with fused phi: one block per batch, 256 threads.
// phi(h1) -> energy (via clisT) -> softmax -> context. Writes attn output,
// cat[:,512:], x[:,V:].
// ---------------------------------------------------------------------------
__global__ void __launch_bounds__(256) k_attn(
        const float* __restrict__ lis,
        const float* __restrict__ Wphi, const float* __restrict__ bphi,
        float* __restrict__ attn_out) {
    __shared__ float h1s[HH];
    __shared__ float cd[MM];
    __shared__ float av[TL];
    __shared__ float rb[TL];
    int b = blockIdx.x, tid = threadIdx.x;
    for (int i = tid; i < HH; i += 256) h1s[i] = g_h1[(size_t)b * HH + i];
    __syncthreads();
    int warp = tid >> 5, lane = tid & 31;
    for (int m = warp; m < MM; m += 8) {
        const float* w = Wphi + (size_t)m * HH;
        float p = 0.f;
#pragma unroll 4
        for (int k = lane; k < HH; k += 32) p = fmaf(w[k], h1s[k], p);
#pragma unroll
        for (int o = 16; o; o >>= 1) p += __shfl_down_sync(0xffffffffu, p, o);
        if (lane == 0) cd[m] = fmaxf(p + bphi[m], 0.f);
    }
    __syncthreads();
    const float* cl = g_clisT + (size_t)b * MM * TL + tid;
    float e = 0.f;
#pragma unroll 8
    for (int m = 0; m < MM; m++) e = fmaf(cd[m], cl[(size_t)m * TL], e);
    rb[tid] = e; __syncthreads();
    for (int o = 128; o > 0; o >>= 1) { if (tid < o) rb[tid] = fmaxf(rb[tid], rb[tid + o]); __syncthreads(); }
    float mx = rb[0]; __syncthreads();
    float p = expf(e - mx);
    rb[tid] = p; __syncthreads();
    for (int o = 128; o > 0; o >>= 1) { if (tid < o) rb[tid] += rb[tid + o]; __syncthreads(); }
    float a = p / rb[0];
    av[tid] = a;
    attn_out[(size_t)b * TL + tid] = a;
    __syncthreads();
    const float* lb = lis + (size_t)b * TL * DL;
#pragma unroll
    for (int dd = 0; dd < 2; dd++) {
        int d = tid + dd * 256;
        float cx = 0.f;
#pragma unroll 4
        for (int t = 0; t < TL; t++) cx = fmaf(av[t], lb[(size_t)t * DL + d], cx);
        g_cat[(size_t)b * CATD + HH + d] = cx;
        g_x[(size_t)b * XD + VV + d] = cx;
    }
}

// ---------------------------------------------------------------------------
// Log-softmax + feedback: one block per batch, 256 threads.
// ---------------------------------------------------------------------------
__global__ void __launch_bounds__(256) k_lsm(
        const float* __restrict__ bc, float* __restrict__ preds_out) {
    __shared__ float lg[2048];
    __shared__ float rb[256];
    int b = blockIdx.x, tid = threadIdx.x;
    float lmax = -1e30f;
    for (int v = tid; v < VV; v += 256) {
        float x = bc[v];
        const float* p = g_pl + (size_t)v * BB + b;
#pragma unroll
        for (int s = 0; s < S_PL; s++) x += p[(size_t)s * LROWS * BB];
        lg[v] = x;
        lmax = fmaxf(lmax, x);
    }
    rb[tid] = lmax; __syncthreads();
    for (int o = 128; o > 0; o >>= 1) { if (tid < o) rb[tid] = fmaxf(rb[tid], rb[tid + o]); __syncthreads(); }
    float mx = rb[0]; __syncthreads();
    float s = 0.f;
    for (int v = tid; v < VV; v += 256) s += expf(lg[v] - mx);
    rb[tid] = s; __syncthreads();
    for (int o = 128; o > 0; o >>= 1) { if (tid < o) rb[tid] += rb[tid + o]; __syncthreads(); }
    float lse = mx + logf(rb[0]);
    for (int v = tid; v < VV; v += 256) {
        float r = lg[v] - lse;
        preds_out[(size_t)b * VV + v] = r;
        g_x[(size_t)b * XD + v] = r;
    }
}

// ---------------------------------------------------------------------------
// Launcher: graph-capturable, deterministic, allocation-free.
// ---------------------------------------------------------------------------
extern "C" void kernel_launch(void* const* d_in, const int* in_sizes, int n_in,
                              void* d_out, int out_size) {
    const float* lis  = (const float*)d_in[0];
    const float* Wih0 = (const float*)d_in[1];
    const float* Whh0 = (const float*)d_in[2];
    const float* bih0 = (const float*)d_in[3];
    const float* bhh0 = (const float*)d_in[4];
    const float* Wih1 = (const float*)d_in[5];
    const float* Whh1 = (const float*)d_in[6];
    const float* bih1 = (const float*)d_in[7];
    const float* bhh1 = (const float*)d_in[8];
    const float* Wphi = (const float*)d_in[9];
    const float* bphi = (const float*)d_in[10];
    const float* Wpsi = (const float*)d_in[11];
    const float* bpsi = (const float*)d_in[12];
    const float* Wc   = (const float*)d_in[13];
    const float* bc   = (const float*)d_in[14];

    float* preds = (float*)d_out;                      // [100,32,2000]
    float* attns = preds + (size_t)NSTEP * BB * VV;    // [100,32,256]

    float *p0, *p1, *h0, *h1, *c0, *c1, *cat;
    cudaGetSymbolAddress((void**)&p0,  g_p0);
    cudaGetSymbolAddress((void**)&p1,  g_p1);
    cudaGetSymbolAddress((void**)&h0,  g_h0);
    cudaGetSymbolAddress((void**)&h1,  g_h1);
    cudaGetSymbolAddress((void**)&c0,  g_c0);
    cudaGetSymbolAddress((void**)&c1,  g_c1);
    cudaGetSymbolAddress((void**)&cat, g_cat);

    k_init<<<(BB * XD + 255) / 256, 256>>>(lis);
    k_psi<<<dim3(8, 4, BB), 128>>>(lis, Wpsi, bpsi);

    for (int t = 0; t < NSTEP; t++) {
        // gates0 (Wih0@x + Whh0@h0) and Whh1@h1_prev : 96 blocks
        k_g0<<<dim3(16, 6), 256>>>(Wih0, Whh0, Whh1);
        // LSTM cell 0
        k_cell<S_P0><<<16, 256>>>(p0, bih0, bhh0, h0, c0, nullptr);
        // Wih1 @ h0_new : 32 blocks
        k_g1<<<dim3(16, 2), 256>>>(Wih1);
        // LSTM cell 1 (+ copy h1 into cat[:, :512])
        k_cell<S_P1><<<16, 256>>>(p1, bih1, bhh1, h1, c1, cat);
        // attention (phi fused): 32 blocks
        k_attn<<<32, 256>>>(lis, Wphi, bphi, attns + (size_t)t * BB * TL);
        // character distribution partials : 64 blocks
        k_glog<<<dim3(16, 4), 256>>>(Wc);
        // log-softmax + feedback
        k_lsm<<<32, 256>>>(bc, preds + (size_t)t * BB * VV);
    }
}